// round 5
// baseline (speedup 1.0000x reference)
#include <cuda_runtime.h>

// Steerable encoder: separable RBF.
//   K1: precompute Ex[i][j] = exp(-0.5 (x_j - X_i.x)^2)        (1M exps)
//   K2: accumulate partial[slice][c][k][j] += Ex * ey-weighted rows
//       (FFMA2 inner loop, 2 j per thread, k-half split per warp pair)
//   K3: per-(channel,pixel) sums over slices (high-MLP)
//   K4: normalize (out1/=out0, out2/=out0)

#define N_AXIS   128
#define NPIX     (N_AXIS * N_AXIS)     // 16384
#define NPTS     8192
#define NSLICE   55                    // 8 ktiles * 55 = 440 CTAs (occ 3)
#define KT       16                    // k-rows per CTA
#define CI       128                   // i-chunk size

__device__ float g_ex[NPTS * N_AXIS];             // 4 MB, L2-resident
__device__ float g_partial[NSLICE * 3 * NPIX];    // [slice][c][k][j]
__device__ float g_sums[3 * NPIX];

__device__ __forceinline__ unsigned long long ffma2(unsigned long long a,
                                                    unsigned long long b,
                                                    unsigned long long c)
{
    unsigned long long d;
    asm("fma.rn.f32x2 %0, %1, %2, %3;" : "=l"(d) : "l"(a), "l"(b), "l"(c));
    return d;
}

__device__ __forceinline__ unsigned long long dup2(float e)
{
    unsigned long long d;
    unsigned int b = __float_as_uint(e);
    asm("mov.b64 %0, {%1, %1};" : "=l"(d) : "r"(b));
    return d;
}

// ---------------- K1: Ex precompute ----------------
__global__ __launch_bounds__(128)
void ex_kernel(const float* __restrict__ X)
{
    const int j = threadIdx.x;
    const float step = 4.0f / 127.0f;
    const float xj = -2.0f + (float)j * step;
    const int i0 = blockIdx.x * 32;
    #pragma unroll 8
    for (int t = 0; t < 32; t++) {
        const int i = i0 + t;
        float dx = xj - __ldg(&X[2 * i]);
        g_ex[i * N_AXIS + j] = __expf(-0.5f * dx * dx);
    }
}

// ---------------- K2: accumulation ----------------
__global__ __launch_bounds__(128, 3)
void se_accum_kernel(const float* __restrict__ X, const float* __restrict__ Y)
{
    __shared__ float sh_a[CI][48];   // [i][k_local*3+c], row = 192B

    const int tid   = threadIdx.x;
    const int lane  = tid & 31;
    const int w     = tid >> 5;
    const int half  = w >> 1;              // k-half: 0 -> rows 0-7, 1 -> rows 8-15
    const int j0    = (w & 1) * 32 + lane; // first j column
    // second column is j0 + 64 (same Ex row, +64 floats)

    const int slice = blockIdx.x;          // 0..NSLICE-1
    const int k0    = blockIdx.y * KT;     // first k-row of tile

    const float step = 4.0f / 127.0f;

    float yk[KT];
    #pragma unroll
    for (int k = 0; k < KT; k++) yk[k] = 2.0f - (float)(k0 + k) * step;

    unsigned long long acc0[12], acc1[12];   // 24 (k,c) scalars x 2 j
    #pragma unroll
    for (int t = 0; t < 12; t++) { acc0[t] = 0ULL; acc1[t] = 0ULL; }

    const int lo = (NPTS * slice) / NSLICE;
    const int hi = (NPTS * (slice + 1)) / NSLICE;

    for (int base = lo; base < hi; base += CI) {
        const int cnt = min(CI, hi - base);

        // ---- cooperative fill: thread tid handles point i = base + tid ----
        if (tid < cnt) {
            const int i = base + tid;
            const float py = __ldg(&X[2 * i + 1]);
            float2 yp = ((const float2*)Y)[i];
            #pragma unroll
            for (int k = 0; k < KT; k++) {
                float dy = yk[k] - py;
                float e  = __expf(-0.5f * dy * dy);
                sh_a[tid][k * 3 + 0] = e;
                sh_a[tid][k * 3 + 1] = e * yp.x;
                sh_a[tid][k * 3 + 2] = e * yp.y;
            }
        }
        __syncthreads();

        // ---- main loop: 2 LDG + 6 LDS.128 + 24 FFMA2 per i per warp ----
        const float* exp0 = g_ex + base * N_AXIS + j0;
        #pragma unroll 2
        for (int ii = 0; ii < cnt; ii++) {
            unsigned long long E0 = dup2(__ldg(exp0));
            unsigned long long E1 = dup2(__ldg(exp0 + 64));
            exp0 += N_AXIS;

            const ulonglong2* row = (const ulonglong2*)(&sh_a[ii][half * 24]);
            #pragma unroll
            for (int u = 0; u < 6; u++) {
                ulonglong2 v = row[u];
                acc0[2 * u + 0] = ffma2(E0, v.x, acc0[2 * u + 0]);
                acc0[2 * u + 1] = ffma2(E0, v.y, acc0[2 * u + 1]);
                acc1[2 * u + 0] = ffma2(E1, v.x, acc1[2 * u + 0]);
                acc1[2 * u + 1] = ffma2(E1, v.y, acc1[2 * u + 1]);
            }
        }
        __syncthreads();
    }

    // ---- write partial sums (coalesced in j within each warp) ----
    float* p = g_partial + slice * (3 * NPIX);
    const int kbase = k0 + half * 8;
    #pragma unroll
    for (int u = 0; u < 12; u++) {
        float a0 = __uint_as_float((unsigned int)(acc0[u] & 0xffffffffULL));
        float b0 = __uint_as_float((unsigned int)(acc0[u] >> 32));
        float a1 = __uint_as_float((unsigned int)(acc1[u] & 0xffffffffULL));
        float b1 = __uint_as_float((unsigned int)(acc1[u] >> 32));
        int m0 = 2 * u, m1 = 2 * u + 1;
        int ka = kbase + m0 / 3, ca = m0 % 3;
        int kb = kbase + m1 / 3, cb = m1 % 3;
        p[ca * NPIX + ka * N_AXIS + j0]      = a0;
        p[ca * NPIX + ka * N_AXIS + j0 + 64] = a1;
        p[cb * NPIX + kb * N_AXIS + j0]      = b0;
        p[cb * NPIX + kb * N_AXIS + j0 + 64] = b1;
    }
}

// ---------------- K3: per-(channel,pixel) sums ----------------
__global__ __launch_bounds__(128)
void sum_kernel()
{
    const int t = blockIdx.x * 128 + threadIdx.x;   // 0..49151
    const float* b = g_partial + t;
    float s = 0.0f;
    #pragma unroll
    for (int sl = 0; sl < NSLICE; sl++)
        s += b[sl * (3 * NPIX)];
    g_sums[t] = s;
}

// ---------------- K4: normalize ----------------
__global__ __launch_bounds__(128)
void norm_kernel(float* __restrict__ out)
{
    const int p = blockIdx.x * 128 + threadIdx.x;
    float s0 = g_sums[p];
    float s1 = g_sums[NPIX + p];
    float s2 = g_sums[2 * NPIX + p];
    float r = 1.0f / s0;
    out[p]            = s0;
    out[NPIX + p]     = s1 * r;
    out[2 * NPIX + p] = s2 * r;
}

extern "C" void kernel_launch(void* const* d_in, const int* in_sizes, int n_in,
                              void* d_out, int out_size)
{
    const float* X = (const float*)d_in[0];
    const float* Y = (const float*)d_in[1];
    float* out = (float*)d_out;

    ex_kernel<<<NPTS / 32, 128>>>(X);
    dim3 grid(NSLICE, N_AXIS / KT);          // 55 x 8 = 440 CTAs
    se_accum_kernel<<<grid, 128>>>(X, Y);
    sum_kernel<<<3 * NPIX / 128, 128>>>();
    norm_kernel<<<NPIX / 128, 128>>>(out);
}

// round 8
// speedup vs baseline: 1.7837x; 1.7837x over previous
#include <cuda_runtime.h>
#include <cuda_bf16.h>
#include <cstdint>

// Steerable encoder as 3-channel bf16-split GEMM on mma.sync (HMMA).
//   out_c[r][j] = sum_i ey[r][i]*w_c[i] * ex[j][i]
// Operand tiles (bf16, hi/lo split):
//   tiles 0..5 = A_{c,p}[r][i]  (p: 0=hi 1=lo), tiles 6..7 = B_p[j][i]
// Stored GEMM-native: g_ops[tile][i>>3][row][i&7]  (16B units).

#define NA     128
#define NPIX   (NA * NA)
#define NPTS   8192
#define NGRP   (NPTS / 8)          // 1024 i8-groups
#define NSPLIT 48                  // grid = 3 x 48 = 144 CTAs
#define KSTEPS 512                 // 8192 / 16

__device__ uint4 g_ops[8 * NGRP * NA];            // 16.8 MB
__device__ float g_part[3 * NSPLIT * NPIX];       // 9.4 MB

// ---------------- helpers ----------------
__device__ __forceinline__ uint32_t smem_u32(const void* p) {
    uint32_t a;
    asm("{ .reg .u64 t; cvta.to.shared.u64 t, %1; cvt.u32.u64 %0, t; }" : "=r"(a) : "l"(p));
    return a;
}
__device__ __forceinline__ void cp_async16(uint32_t dst, const void* src) {
    asm volatile("cp.async.cg.shared.global [%0], [%1], 16;" :: "r"(dst), "l"(src));
}
__device__ __forceinline__ void ldsm4(uint32_t addr, uint32_t& r0, uint32_t& r1,
                                      uint32_t& r2, uint32_t& r3) {
    asm volatile("ldmatrix.sync.aligned.m8n8.x4.shared.b16 {%0,%1,%2,%3}, [%4];"
                 : "=r"(r0), "=r"(r1), "=r"(r2), "=r"(r3) : "r"(addr));
}
__device__ __forceinline__ void mma_bf16(float* d, const uint32_t* a, const uint32_t* b) {
    asm volatile("mma.sync.aligned.m16n8k16.row.col.f32.bf16.bf16.f32 "
                 "{%0,%1,%2,%3}, {%4,%5,%6,%7}, {%8,%9}, {%0,%1,%2,%3};"
                 : "+f"(d[0]), "+f"(d[1]), "+f"(d[2]), "+f"(d[3])
                 : "r"(a[0]), "r"(a[1]), "r"(a[2]), "r"(a[3]), "r"(b[0]), "r"(b[1]));
}
__device__ __forceinline__ void split_bf16(float v, unsigned short& h, unsigned short& l) {
    __nv_bfloat16 bh = __float2bfloat16(v);
    h = __bfloat16_as_ushort(bh);
    l = __bfloat16_as_ushort(__float2bfloat16(v - __bfloat162float(bh)));
}

// ---------------- K1: materialize operands ----------------
// blocks 0..127: A tiles for i-range [bid*64, +64); blocks 128..255: B tiles.
__global__ __launch_bounds__(128)
void mat_kernel(const float* __restrict__ X, const float* __restrict__ Y)
{
    __shared__ float sp[64], sy0[64], sy1[64];
    const int tid = threadIdx.x;
    const int bid = blockIdx.x;
    const bool isA = bid < 128;
    const int ibase = (isA ? bid : bid - 128) * 64;
    const float step = 4.0f / 127.0f;

    if (tid < 64) {
        int i = ibase + tid;
        if (isA) {
            sp[tid] = X[2 * i + 1];
            float2 yv = ((const float2*)Y)[i];
            sy0[tid] = yv.x; sy1[tid] = yv.y;
        } else {
            sp[tid] = X[2 * i];
        }
    }
    __syncthreads();

    const float coord = isA ? (2.0f - (float)tid * step) : (-2.0f + (float)tid * step);

    if (isA) {
        for (int g = 0; g < 8; g++) {
            uint32_t w[6][4];
            #pragma unroll
            for (int ee = 0; ee < 4; ee++) {
                #pragma unroll
                for (int hf = 0; hf < 2; hf++) {
                    int il = g * 8 + ee * 2 + hf;
                    float d = coord - sp[il];
                    float e = __expf(-0.5f * d * d);
                    float v0 = e, v1 = e * sy0[il], v2 = e * sy1[il];
                    unsigned short h, l;
                    split_bf16(v0, h, l);
                    if (hf == 0) { w[0][ee] = h; w[1][ee] = l; }
                    else { w[0][ee] |= (uint32_t)h << 16; w[1][ee] |= (uint32_t)l << 16; }
                    split_bf16(v1, h, l);
                    if (hf == 0) { w[2][ee] = h; w[3][ee] = l; }
                    else { w[2][ee] |= (uint32_t)h << 16; w[3][ee] |= (uint32_t)l << 16; }
                    split_bf16(v2, h, l);
                    if (hf == 0) { w[4][ee] = h; w[5][ee] = l; }
                    else { w[4][ee] |= (uint32_t)h << 16; w[5][ee] |= (uint32_t)l << 16; }
                }
            }
            int gg = bid * 8 + g;
            #pragma unroll
            for (int t = 0; t < 6; t++)
                g_ops[(t * NGRP + gg) * NA + tid] = make_uint4(w[t][0], w[t][1], w[t][2], w[t][3]);
        }
    } else {
        for (int g = 0; g < 8; g++) {
            uint32_t w[2][4];
            #pragma unroll
            for (int ee = 0; ee < 4; ee++) {
                #pragma unroll
                for (int hf = 0; hf < 2; hf++) {
                    int il = g * 8 + ee * 2 + hf;
                    float d = coord - sp[il];
                    float e = __expf(-0.5f * d * d);
                    unsigned short h, l;
                    split_bf16(e, h, l);
                    if (hf == 0) { w[0][ee] = h; w[1][ee] = l; }
                    else { w[0][ee] |= (uint32_t)h << 16; w[1][ee] |= (uint32_t)l << 16; }
                }
            }
            int gg = (bid - 128) * 8 + g;
            g_ops[(6 * NGRP + gg) * NA + tid] = make_uint4(w[0][0], w[0][1], w[0][2], w[0][3]);
            g_ops[(7 * NGRP + gg) * NA + tid] = make_uint4(w[1][0], w[1][1], w[1][2], w[1][3]);
        }
    }
}

// ---------------- K2: split-K HMMA GEMM ----------------
// smem stage (16KB): parts p=0..3 (Ah,Al,Bh,Bl), each [kg(2)][row(128)][16B].
__device__ __forceinline__ void prefetch_stage(uint32_t sbase, int buf, int c, int ks, int tid)
{
    uint32_t dbase = sbase + buf * 16384;
    const int gl = tid >> 7, r = tid & 127;
    #pragma unroll
    for (int ph = 0; ph < 4; ph++) {
        int tile = (ph == 0) ? 2 * c : (ph == 1) ? 2 * c + 1 : (ph == 2) ? 6 : 7;
        const uint4* src = g_ops + (tile * NGRP + 2 * ks + gl) * NA + r;
        cp_async16(dbase + ph * 4096 + tid * 16, src);
    }
    asm volatile("cp.async.commit_group;");
}

__global__ __launch_bounds__(256)
void gemm_kernel()
{
    __shared__ __align__(16) char smem[2 * 16384];
    const uint32_t sb = smem_u32(smem);
    const int tid = threadIdx.x;
    const int lane = tid & 31, wid = tid >> 5;
    const int wm = wid & 3, wn = wid >> 2;     // warp tile: rows [wm*32,+32), cols [wn*64,+64)
    const int c = blockIdx.x, s = blockIdx.y;
    const int lo = (KSTEPS * s) / NSPLIT, hi = (KSTEPS * (s + 1)) / NSPLIT;

    float acc[2][8][4];
    #pragma unroll
    for (int a = 0; a < 2; a++)
        #pragma unroll
        for (int b = 0; b < 8; b++)
            #pragma unroll
            for (int d = 0; d < 4; d++) acc[a][b][d] = 0.0f;

    const int q = lane >> 3, rin = lane & 7;

    prefetch_stage(sb, 0, c, lo, tid);

    for (int ks = lo; ks < hi; ks++) {
        int buf = (ks - lo) & 1;
        bool more = (ks + 1 < hi);
        if (more) {
            prefetch_stage(sb, buf ^ 1, c, ks + 1, tid);
            asm volatile("cp.async.wait_group 1;" ::: "memory");
        } else {
            asm volatile("cp.async.wait_group 0;" ::: "memory");
        }
        __syncthreads();

        uint32_t base = sb + buf * 16384;

        // A fragments (2 m-tiles, hi+lo)
        uint32_t ah[2][4], al[2][4];
        #pragma unroll
        for (int mt = 0; mt < 2; mt++) {
            int rr = (wm * 2 + mt) * 16 + (q & 1) * 8 + rin;
            uint32_t ad = base + ((q >> 1) * 128 + rr) * 16;
            ldsm4(ad,        ah[mt][0], ah[mt][1], ah[mt][2], ah[mt][3]);
            ldsm4(ad + 4096, al[mt][0], al[mt][1], al[mt][2], al[mt][3]);
        }

        // B fragments in 4 chunks of 2 n-tiles; 12 MMA per chunk
        #pragma unroll
        for (int d = 0; d < 4; d++) {
            int jj = wn * 64 + d * 16 + (q >> 1) * 8 + rin;
            uint32_t bd = base + 8192 + ((q & 1) * 128 + jj) * 16;
            uint32_t bh[4], bl[4];
            ldsm4(bd,        bh[0], bh[1], bh[2], bh[3]);
            ldsm4(bd + 4096, bl[0], bl[1], bl[2], bl[3]);
            #pragma unroll
            for (int half = 0; half < 2; half++) {
                uint32_t bhp[2] = { bh[2 * half], bh[2 * half + 1] };
                uint32_t blp[2] = { bl[2 * half], bl[2 * half + 1] };
                #pragma unroll
                for (int mt = 0; mt < 2; mt++) {
                    float* D = acc[mt][2 * d + half];
                    mma_bf16(D, ah[mt], bhp);   // Ah*Bh
                    mma_bf16(D, ah[mt], blp);   // Ah*Bl
                    mma_bf16(D, al[mt], bhp);   // Al*Bh
                }
            }
        }
        __syncthreads();
    }

    // epilogue: write partial plane [c][s][r][j]
    float* plane = g_part + (c * NSPLIT + s) * NPIX;
    const int gid = lane >> 2, tig = lane & 3;
    #pragma unroll
    for (int mt = 0; mt < 2; mt++) {
        #pragma unroll
        for (int nt = 0; nt < 8; nt++) {
            int m0 = wm * 32 + mt * 16 + gid;
            int j0 = wn * 64 + nt * 8 + 2 * tig;
            float2 v01 = make_float2(acc[mt][nt][0], acc[mt][nt][1]);
            float2 v23 = make_float2(acc[mt][nt][2], acc[mt][nt][3]);
            *(float2*)(plane + m0 * NA + j0)       = v01;
            *(float2*)(plane + (m0 + 8) * NA + j0) = v23;
        }
    }
}

// ---------------- K3: reduce splits + normalize ----------------
__global__ __launch_bounds__(128)
void reduce_kernel(float* __restrict__ out)
{
    const int p = blockIdx.x * 128 + threadIdx.x;   // r*128 + j
    float s0 = 0.0f, s1 = 0.0f, s2 = 0.0f;
    #pragma unroll
    for (int s = 0; s < NSPLIT; s++) {
        s0 += __ldcg(&g_part[(0 * NSPLIT + s) * NPIX + p]);
        s1 += __ldcg(&g_part[(1 * NSPLIT + s) * NPIX + p]);
        s2 += __ldcg(&g_part[(2 * NSPLIT + s) * NPIX + p]);
    }
    float r = 1.0f / s0;
    out[p]            = s0;
    out[NPIX + p]     = s1 * r;
    out[2 * NPIX + p] = s2 * r;
}

extern "C" void kernel_launch(void* const* d_in, const int* in_sizes, int n_in,
                              void* d_out, int out_size)
{
    const float* X = (const float*)d_in[0];
    const float* Y = (const float*)d_in[1];
    float* out = (float*)d_out;

    mat_kernel<<<256, 128>>>(X, Y);
    gemm_kernel<<<dim3(3, NSPLIT), 256>>>();
    reduce_kernel<<<NPIX / 128, 128>>>(out);
}

// round 9
// speedup vs baseline: 1.9771x; 1.1084x over previous
#include <cuda_runtime.h>
#include <cuda_bf16.h>
#include <cstdint>

// Steerable encoder as 3-channel bf16-split GEMM on mma.sync (HMMA).
//   out_c[r][j] = sum_i ey[r][i]*w_c[i] * ex[j][i]
// Operand tiles (bf16, hi/lo split):
//   tiles 0..5 = A_{c,p}[r][i]  (p: 0=hi 1=lo), tiles 6..7 = B_p[j][i]
// Stored GEMM-native: g_ops[tile][i>>3][row][i&7]  (16B units).

#define NA     128
#define NPIX   (NA * NA)
#define NPTS   8192
#define NGRP   (NPTS / 8)          // 1024 i8-groups
#define NSPLIT 48                  // grid = 3 x 48 = 144 CTAs
#define KSTEPS 512                 // 8192 / 16

__device__ uint4 g_ops[8 * NGRP * NA];            // 16.8 MB
__device__ float g_part[3 * NSPLIT * NPIX];       // 9.4 MB

// ---------------- helpers ----------------
__device__ __forceinline__ uint32_t smem_u32(const void* p) {
    uint32_t a;
    asm("{ .reg .u64 t; cvta.to.shared.u64 t, %1; cvt.u32.u64 %0, t; }" : "=r"(a) : "l"(p));
    return a;
}
__device__ __forceinline__ void cp_async16(uint32_t dst, const void* src) {
    asm volatile("cp.async.cg.shared.global [%0], [%1], 16;" :: "r"(dst), "l"(src));
}
__device__ __forceinline__ void ldsm4(uint32_t addr, uint32_t& r0, uint32_t& r1,
                                      uint32_t& r2, uint32_t& r3) {
    asm volatile("ldmatrix.sync.aligned.m8n8.x4.shared.b16 {%0,%1,%2,%3}, [%4];"
                 : "=r"(r0), "=r"(r1), "=r"(r2), "=r"(r3) : "r"(addr));
}
__device__ __forceinline__ void mma_bf16(float* d, const uint32_t* a, const uint32_t* b) {
    asm volatile("mma.sync.aligned.m16n8k16.row.col.f32.bf16.bf16.f32 "
                 "{%0,%1,%2,%3}, {%4,%5,%6,%7}, {%8,%9}, {%0,%1,%2,%3};"
                 : "+f"(d[0]), "+f"(d[1]), "+f"(d[2]), "+f"(d[3])
                 : "r"(a[0]), "r"(a[1]), "r"(a[2]), "r"(a[3]), "r"(b[0]), "r"(b[1]));
}

// Split a pair (a=even i, b=odd i) into packed bf16x2 hi and lo words.
// hi: truncated top-16 of each fp32 (one PRMT). lo: residual rounded to bf16
// (one cvt.rn.bf16x2 packs both).
__device__ __forceinline__ void pack_pair(float a, float b, uint32_t& hi, uint32_t& lo) {
    uint32_t ua = __float_as_uint(a), ub = __float_as_uint(b);
    hi = __byte_perm(ua, ub, 0x7632);          // low16 = top16(a), high16 = top16(b)
    float la = a - __uint_as_float(ua & 0xFFFF0000u);
    float lb = b - __uint_as_float(ub & 0xFFFF0000u);
    asm("cvt.rn.bf16x2.f32 %0, %1, %2;" : "=r"(lo) : "f"(lb), "f"(la));
}

// ---------------- K1: materialize operands ----------------
// 1024 blocks x 128 threads. Blocks 0..511: A tiles, i-range [bid*16,+16).
// Blocks 512..1023: B tiles, i-range [(bid-512)*16,+16). Thread = row.
__global__ __launch_bounds__(128)
void mat_kernel(const float* __restrict__ X, const float* __restrict__ Y)
{
    __shared__ float sp[16], sy0[16], sy1[16];
    const int tid = threadIdx.x;               // row (k for A, j for B)
    const int bid = blockIdx.x;
    const bool isA = bid < 512;
    const int ibase = (isA ? bid : bid - 512) * 16;
    const float step = 4.0f / 127.0f;

    if (tid < 16) {
        int i = ibase + tid;
        if (isA) {
            sp[tid] = X[2 * i + 1];
            float2 yv = ((const float2*)Y)[i];
            sy0[tid] = yv.x; sy1[tid] = yv.y;
        } else {
            sp[tid] = X[2 * i];
        }
    }
    __syncthreads();

    const float coord = isA ? (2.0f - (float)tid * step) : (-2.0f + (float)tid * step);

    #pragma unroll
    for (int g = 0; g < 2; g++) {
        const int grp = (ibase >> 3) + g;      // i8-group index
        float e[8];
        #pragma unroll
        for (int u = 0; u < 8; u++) {
            float d = coord - sp[g * 8 + u];
            e[u] = __expf(-0.5f * d * d);
        }
        if (isA) {
            uint32_t w[6][4];
            #pragma unroll
            for (int ee = 0; ee < 4; ee++) {
                const int u0 = 2 * ee, u1 = 2 * ee + 1;
                const int l0 = g * 8 + u0, l1 = g * 8 + u1;
                pack_pair(e[u0],            e[u1],            w[0][ee], w[1][ee]);
                pack_pair(e[u0] * sy0[l0],  e[u1] * sy0[l1],  w[2][ee], w[3][ee]);
                pack_pair(e[u0] * sy1[l0],  e[u1] * sy1[l1],  w[4][ee], w[5][ee]);
            }
            #pragma unroll
            for (int t = 0; t < 6; t++)
                g_ops[(t * NGRP + grp) * NA + tid] =
                    make_uint4(w[t][0], w[t][1], w[t][2], w[t][3]);
        } else {
            uint32_t w[2][4];
            #pragma unroll
            for (int ee = 0; ee < 4; ee++)
                pack_pair(e[2 * ee], e[2 * ee + 1], w[0][ee], w[1][ee]);
            g_ops[(6 * NGRP + grp) * NA + tid] = make_uint4(w[0][0], w[0][1], w[0][2], w[0][3]);
            g_ops[(7 * NGRP + grp) * NA + tid] = make_uint4(w[1][0], w[1][1], w[1][2], w[1][3]);
        }
    }
}

// ---------------- K2: split-K HMMA GEMM ----------------
// smem stage (16KB): parts p=0..3 (Ah,Al,Bh,Bl), each [kg(2)][row(128)][16B].
__device__ __forceinline__ void prefetch_stage(uint32_t sbase, int buf, int c, int ks, int tid)
{
    uint32_t dbase = sbase + buf * 16384;
    const int gl = tid >> 7, r = tid & 127;
    #pragma unroll
    for (int ph = 0; ph < 4; ph++) {
        int tile = (ph == 0) ? 2 * c : (ph == 1) ? 2 * c + 1 : (ph == 2) ? 6 : 7;
        const uint4* src = g_ops + (tile * NGRP + 2 * ks + gl) * NA + r;
        cp_async16(dbase + ph * 4096 + tid * 16, src);
    }
    asm volatile("cp.async.commit_group;");
}

__global__ __launch_bounds__(256)
void gemm_kernel()
{
    __shared__ __align__(16) char smem[2 * 16384];
    const uint32_t sb = smem_u32(smem);
    const int tid = threadIdx.x;
    const int lane = tid & 31, wid = tid >> 5;
    const int wm = wid & 3, wn = wid >> 2;     // warp tile: rows [wm*32,+32), cols [wn*64,+64)
    const int c = blockIdx.x, s = blockIdx.y;
    const int lo = (KSTEPS * s) / NSPLIT, hi = (KSTEPS * (s + 1)) / NSPLIT;

    float acc[2][8][4];
    #pragma unroll
    for (int a = 0; a < 2; a++)
        #pragma unroll
        for (int b = 0; b < 8; b++)
            #pragma unroll
            for (int d = 0; d < 4; d++) acc[a][b][d] = 0.0f;

    const int q = lane >> 3, rin = lane & 7;

    prefetch_stage(sb, 0, c, lo, tid);

    for (int ks = lo; ks < hi; ks++) {
        int buf = (ks - lo) & 1;
        bool more = (ks + 1 < hi);
        if (more) {
            prefetch_stage(sb, buf ^ 1, c, ks + 1, tid);
            asm volatile("cp.async.wait_group 1;" ::: "memory");
        } else {
            asm volatile("cp.async.wait_group 0;" ::: "memory");
        }
        __syncthreads();

        uint32_t base = sb + buf * 16384;

        // A fragments (2 m-tiles, hi+lo)
        uint32_t ah[2][4], al[2][4];
        #pragma unroll
        for (int mt = 0; mt < 2; mt++) {
            int rr = (wm * 2 + mt) * 16 + (q & 1) * 8 + rin;
            uint32_t ad = base + ((q >> 1) * 128 + rr) * 16;
            ldsm4(ad,        ah[mt][0], ah[mt][1], ah[mt][2], ah[mt][3]);
            ldsm4(ad + 4096, al[mt][0], al[mt][1], al[mt][2], al[mt][3]);
        }

        // B fragments in 4 chunks of 2 n-tiles; 12 MMA per chunk
        #pragma unroll
        for (int d = 0; d < 4; d++) {
            int jj = wn * 64 + d * 16 + (q >> 1) * 8 + rin;
            uint32_t bd = base + 8192 + ((q & 1) * 128 + jj) * 16;
            uint32_t bh[4], bl[4];
            ldsm4(bd,        bh[0], bh[1], bh[2], bh[3]);
            ldsm4(bd + 4096, bl[0], bl[1], bl[2], bl[3]);
            #pragma unroll
            for (int half = 0; half < 2; half++) {
                uint32_t bhp[2] = { bh[2 * half], bh[2 * half + 1] };
                uint32_t blp[2] = { bl[2 * half], bl[2 * half + 1] };
                #pragma unroll
                for (int mt = 0; mt < 2; mt++) {
                    float* D = acc[mt][2 * d + half];
                    mma_bf16(D, ah[mt], bhp);   // Ah*Bh
                    mma_bf16(D, ah[mt], blp);   // Ah*Bl
                    mma_bf16(D, al[mt], bhp);   // Al*Bh
                }
            }
        }
        __syncthreads();
    }

    // epilogue: write partial plane [c][s][r][j]
    float* plane = g_part + (c * NSPLIT + s) * NPIX;
    const int gid = lane >> 2, tig = lane & 3;
    #pragma unroll
    for (int mt = 0; mt < 2; mt++) {
        #pragma unroll
        for (int nt = 0; nt < 8; nt++) {
            int m0 = wm * 32 + mt * 16 + gid;
            int j0 = wn * 64 + nt * 8 + 2 * tig;
            float2 v01 = make_float2(acc[mt][nt][0], acc[mt][nt][1]);
            float2 v23 = make_float2(acc[mt][nt][2], acc[mt][nt][3]);
            *(float2*)(plane + m0 * NA + j0)       = v01;
            *(float2*)(plane + (m0 + 8) * NA + j0) = v23;
        }
    }
}

// ---------------- K3: reduce splits + normalize ----------------
__global__ __launch_bounds__(256)
void reduce_kernel(float* __restrict__ out)
{
    const int p = blockIdx.x * 256 + threadIdx.x;   // r*128 + j
    float s0 = 0.0f, s1 = 0.0f, s2 = 0.0f;
    #pragma unroll
    for (int s = 0; s < NSPLIT; s++) {
        s0 += __ldcg(&g_part[(0 * NSPLIT + s) * NPIX + p]);
        s1 += __ldcg(&g_part[(1 * NSPLIT + s) * NPIX + p]);
        s2 += __ldcg(&g_part[(2 * NSPLIT + s) * NPIX + p]);
    }
    float r = 1.0f / s0;
    out[p]            = s0;
    out[NPIX + p]     = s1 * r;
    out[2 * NPIX + p] = s2 * r;
}

extern "C" void kernel_launch(void* const* d_in, const int* in_sizes, int n_in,
                              void* d_out, int out_size)
{
    const float* X = (const float*)d_in[0];
    const float* Y = (const float*)d_in[1];
    float* out = (float*)d_out;

    mat_kernel<<<1024, 128>>>(X, Y);
    gemm_kernel<<<dim3(3, NSPLIT), 256>>>();
    reduce_kernel<<<NPIX / 256, 256>>>(out);
}